// round 1
// baseline (speedup 1.0000x reference)
#include <cuda_runtime.h>
#include <math.h>

#define NN 50000
#define EE 800000
#define NF  512
#define NH  128
#define NC  16
#define EPSF 1e-9f

// ---------------- scratch (static device allocations) ----------------
__device__ float g_h1[NN * NH];     // x @ fc1_w
__device__ float g_h[NN * NH];      // elu(rst1 + perm) -> layer2 input
__device__ float g_rst1[NN * NH];
__device__ float g_hlatp[NN * NC];
__device__ float g_hlatp2[NN * NC];
__device__ float g_h2[NN * NC];
__device__ float g_rst2[NN * NC];
__device__ float g_el1[NN], g_er1[NN];
__device__ float g_el2[NN], g_er2[NN];
__device__ float g_indeg[NN];
__device__ float g_outw1[NN], g_inw1[NN], g_outw2[NN], g_inw2[NN];
__device__ float g_ew1[EE], g_ew2[EE];
__device__ float g_lp;
// [0]=betaw1 [1]=w01 [2]=w11 [3]=permc1 [4]=betaw2 [5]=w02 [6]=w12 [7]=permc2
__device__ float g_scal[8];

// ---------------- helpers ----------------
__device__ __forceinline__ float eluf(float x) { return x > 0.f ? x : expm1f(x); }
__device__ __forceinline__ float leakyf(float x) { return x > 0.f ? x : 0.2f * x; }

__device__ __forceinline__ void red_add_v4(float* addr, float4 v) {
    asm volatile("red.global.add.v4.f32 [%0], {%1,%2,%3,%4};"
                 :: "l"(addr), "f"(v.x), "f"(v.y), "f"(v.z), "f"(v.w) : "memory");
}

// ---------------- zero scratch ----------------
__global__ void k_zero() {
    int i = blockIdx.x * blockDim.x + threadIdx.x;
    int st = gridDim.x * blockDim.x;
    for (int j = i; j < NN * NH; j += st) g_rst1[j] = 0.f;
    for (int j = i; j < NN * NC; j += st) g_rst2[j] = 0.f;
    for (int j = i; j < NN; j += st) {
        g_indeg[j] = 0.f;
        g_outw1[j] = 0.f; g_inw1[j] = 0.f;
        g_outw2[j] = 0.f; g_inw2[j] = 0.f;
    }
    if (i == 0) g_lp = 0.f;
}

// ---------------- derived scalars ----------------
__global__ void k_scalars(const float* beta1, const float* aw1, const float* theta1,
                          const float* beta2, const float* aw2, const float* theta2) {
    if (threadIdx.x == 0) {
        g_scal[0] = 2.f / (expf(-beta1[0]) + 1.f);
        float m1 = fmaxf(aw1[0], aw1[1]);
        float a0 = expf(aw1[0] - m1), a1 = expf(aw1[1] - m1);
        g_scal[1] = a0 / (a0 + a1);
        g_scal[2] = a1 / (a0 + a1);
        g_scal[3] = EPSF / (expf(-theta1[0]) + 1.f);

        g_scal[4] = 2.f / (expf(-beta2[0]) + 1.f);
        float m2 = fmaxf(aw2[0], aw2[1]);
        float b0 = expf(aw2[0] - m2), b1 = expf(aw2[1] - m2);
        g_scal[5] = b0 / (b0 + b1);
        g_scal[6] = b1 / (b0 + b1);
        g_scal[7] = EPSF / (expf(-theta2[0]) + 1.f);
    }
}

// ---------------- hlatp = elu(latp@sl_w + sl_b); hlatp2 = elu(hlatp@slo_w + slo_b) ----------------
__global__ void k_latp(const float* __restrict__ latp,
                       const float* __restrict__ sl_w, const float* __restrict__ sl_b,
                       const float* __restrict__ slo_w, const float* __restrict__ slo_b) {
    __shared__ float W1[NC * NC], W2[NC * NC], B1[NC], B2[NC];
    int t = threadIdx.x;
    if (t < NC * NC) { W1[t] = sl_w[t]; W2[t] = slo_w[t]; }
    if (t < NC) { B1[t] = sl_b[t]; B2[t] = slo_b[t]; }
    __syncthreads();
    int n = blockIdx.x * blockDim.x + t;
    if (n >= NN) return;

    float in[NC], t1[NC];
#pragma unroll
    for (int j = 0; j < NC; j++) in[j] = latp[n * NC + j];
#pragma unroll
    for (int c = 0; c < NC; c++) {
        float acc = B1[c];
#pragma unroll
        for (int j = 0; j < NC; j++) acc += in[j] * W1[j * NC + c];
        t1[c] = eluf(acc);
        g_hlatp[n * NC + c] = t1[c];
    }
#pragma unroll
    for (int c = 0; c < NC; c++) {
        float acc = B2[c];
#pragma unroll
        for (int j = 0; j < NC; j++) acc += t1[j] * W2[j * NC + c];
        g_hlatp2[n * NC + c] = eluf(acc);
    }
}

// ---------------- GEMM: h1 = x(50000x512) @ fc1_w(512x128) ----------------
#define GBM 64
#define GBK 16
#define GBN 128
__global__ void k_gemm1(const float* __restrict__ x, const float* __restrict__ w) {
    __shared__ float As[GBK][GBM];
    __shared__ float Bs[GBK][GBN];
    int tid = threadIdx.x;              // 256
    int m0 = blockIdx.x * GBM;
    int ty = tid >> 5;                  // 0..7 (8 rows each)
    int tx = tid & 31;                  // 0..31 (4 cols each)
    float acc[8][4];
#pragma unroll
    for (int i = 0; i < 8; i++)
#pragma unroll
        for (int j = 0; j < 4; j++) acc[i][j] = 0.f;

    int lm = tid & 63;                  // A-load row
    int lk4 = (tid >> 6) << 2;          // A-load k (4 wide)
    int bk = tid >> 5;                  // B-load row
    int bn4 = (tid & 31) << 2;          // B-load col (4 wide)

    for (int k0 = 0; k0 < NF; k0 += GBK) {
        int gm = m0 + lm;
        float4 av = make_float4(0.f, 0.f, 0.f, 0.f);
        if (gm < NN) av = *(const float4*)(x + (size_t)gm * NF + k0 + lk4);
        As[lk4 + 0][lm] = av.x;
        As[lk4 + 1][lm] = av.y;
        As[lk4 + 2][lm] = av.z;
        As[lk4 + 3][lm] = av.w;

        *(float4*)&Bs[bk][bn4]     = *(const float4*)(w + (size_t)(k0 + bk) * GBN + bn4);
        *(float4*)&Bs[bk + 8][bn4] = *(const float4*)(w + (size_t)(k0 + bk + 8) * GBN + bn4);
        __syncthreads();

#pragma unroll
        for (int k = 0; k < GBK; k++) {
            float4 bv = *(const float4*)&Bs[k][tx << 2];
#pragma unroll
            for (int i = 0; i < 8; i++) {
                float aval = As[k][(ty << 3) + i];
                acc[i][0] += aval * bv.x;
                acc[i][1] += aval * bv.y;
                acc[i][2] += aval * bv.z;
                acc[i][3] += aval * bv.w;
            }
        }
        __syncthreads();
    }
#pragma unroll
    for (int i = 0; i < 8; i++) {
        int gm = m0 + (ty << 3) + i;
        if (gm < NN) {
            float4 v = make_float4(acc[i][0], acc[i][1], acc[i][2], acc[i][3]);
            *(float4*)&g_h1[(size_t)gm * NH + (tx << 2)] = v;
        }
    }
}

// ---------------- el1/er1 = leaky(h1) . w_u / w_v ----------------
__global__ void k_eler1(const float* __restrict__ wu, const float* __restrict__ wv) {
    int gt = blockIdx.x * blockDim.x + threadIdx.x;
    int lane = threadIdx.x & 31;
    int gw = gt >> 5;
    int nw = (gridDim.x * blockDim.x) >> 5;
    float4 u = ((const float4*)wu)[lane];
    float4 v = ((const float4*)wv)[lane];
    for (int n = gw; n < NN; n += nw) {
        float4 h = ((const float4*)(g_h1 + (size_t)n * NH))[lane];
        float lx = leakyf(h.x), ly = leakyf(h.y), lz = leakyf(h.z), lw = leakyf(h.w);
        float pu = lx * u.x + ly * u.y + lz * u.z + lw * u.w;
        float pv = lx * v.x + ly * v.y + lz * v.z + lw * v.w;
#pragma unroll
        for (int off = 16; off; off >>= 1) {
            pu += __shfl_down_sync(0xffffffffu, pu, off);
            pv += __shfl_down_sync(0xffffffffu, pv, off);
        }
        if (lane == 0) { g_el1[n] = pu; g_er1[n] = pv; }
    }
}

// ---------------- layer1 edge pass A: ew1, outw1, inw1, indeg ----------------
__global__ void k_edgeA1(const int* __restrict__ src, const int* __restrict__ dst,
                         const float* __restrict__ ws1) {
    int gt = blockIdx.x * blockDim.x + threadIdx.x;
    int lane = threadIdx.x & 31;
    int gw = gt >> 5;
    int nw = (gridDim.x * blockDim.x) >> 5;
    float wsv = (lane < NC) ? ws1[lane] : 0.f;
    float bw = g_scal[0], w0 = g_scal[1], w1 = g_scal[2];

    for (int e = gw; e < EE; e += nw) {
        int s = src[e], d = dst[e];
        float4 a = ((const float4*)(g_h1 + (size_t)s * NH))[lane];
        float4 b = ((const float4*)(g_h1 + (size_t)d * NH))[lane];
        float dx = a.x - b.x, dy = a.y - b.y, dz = a.z - b.z, dw = a.w - b.w;
        float sdf = dx * dx + dy * dy + dz * dz + dw * dw;
        float sds = 0.f, st = 0.f;
        if (lane < NC) {
            float ps = g_hlatp[(size_t)s * NC + lane];
            float pd = g_hlatp[(size_t)d * NC + lane];
            float df = ps - pd;
            sds = df * df;
            st = ps * wsv * pd;
        }
#pragma unroll
        for (int off = 16; off; off >>= 1) {
            sdf += __shfl_down_sync(0xffffffffu, sdf, off);
            sds += __shfl_down_sync(0xffffffffu, sds, off);
            st  += __shfl_down_sync(0xffffffffu, st, off);
        }
        if (lane == 0) {
            float ee = g_el1[s] + g_er1[d] + st;
            float ew = expf(ee - bw * (w0 * sdf + w1 * sds)) + EPSF;
            g_ew1[e] = ew;
            atomicAdd(&g_outw1[s], ew);
            atomicAdd(&g_inw1[d], ew);
            atomicAdd(&g_indeg[d], 1.0f);
        }
    }
}

// ---------------- layer1 edge pass B: rst1[dst] += h1[src] * a ----------------
__global__ void k_edgeB1(const int* __restrict__ src, const int* __restrict__ dst) {
    int gt = blockIdx.x * blockDim.x + threadIdx.x;
    int lane = threadIdx.x & 31;
    int gw = gt >> 5;
    int nw = (gridDim.x * blockDim.x) >> 5;
    for (int e = gw; e < EE; e += nw) {
        int s = src[e], d = dst[e];
        float a = 0.f;
        if (lane == 0)
            a = rsqrtf(g_outw1[s]) * rsqrtf(g_inw1[d]) * g_ew1[e];
        a = __shfl_sync(0xffffffffu, a, 0);
        float4 h = ((const float4*)(g_h1 + (size_t)s * NH))[lane];
        h.x *= a; h.y *= a; h.z *= a; h.w *= a;
        red_add_v4(&g_rst1[(size_t)d * NH + (lane << 2)], h);
    }
}

// ---------------- h = elu(rst1 + h1 * perm1) ----------------
__global__ void k_combine1() {
    int i = blockIdx.x * blockDim.x + threadIdx.x;
    int st = gridDim.x * blockDim.x;
    float pc = g_scal[3];
    for (int j = i; j < NN * NH; j += st) {
        int n = j >> 7;
        float perm = pc / (g_indeg[n] + EPSF);
        g_h[j] = eluf(g_rst1[j] + g_h1[j] * perm);
    }
}

// ---------------- h2 = h @ fc2_w ; el2/er2 ----------------
__global__ void k_fc2(const float* __restrict__ w, const float* __restrict__ wu,
                      const float* __restrict__ wv) {
    __shared__ float Ws[NH * NC];
    int t = threadIdx.x;
    for (int j = t; j < NH * NC; j += blockDim.x) Ws[j] = w[j];
    __syncthreads();

    int lane = t & 31;
    int c = lane & 15;
    int half = (lane >> 4);
    int gw = (blockIdx.x * blockDim.x + t) >> 5;
    int nw = (gridDim.x * blockDim.x) >> 5;
    float wuc = wu[c], wvc = wv[c];

    for (int n = gw * 2 + half; n < NN; n += nw * 2) {
        const float* hr = g_h + (size_t)n * NH;
        float acc = 0.f;
#pragma unroll
        for (int k = 0; k < NH; k++) acc += hr[k] * Ws[k * NC + c];
        g_h2[(size_t)n * NC + c] = acc;
        float lr = leakyf(acc);
        float pu = lr * wuc, pv = lr * wvc;
#pragma unroll
        for (int off = 8; off; off >>= 1) {
            pu += __shfl_down_sync(0xffffffffu, pu, off, 16);
            pv += __shfl_down_sync(0xffffffffu, pv, off, 16);
        }
        if (c == 0) { g_el2[n] = pu; g_er2[n] = pv; }
    }
}

// ---------------- layer2 edge pass A: ew2, outw2, inw2, lp ----------------
__global__ void k_edgeA2(const int* __restrict__ src, const int* __restrict__ dst,
                         const float* __restrict__ ws2, const float* __restrict__ wts) {
    __shared__ float redbuf[256];
    int t = threadIdx.x;
    int c = t & 15;
    int grp = (blockIdx.x * blockDim.x + t) >> 4;
    int ngr = (gridDim.x * blockDim.x) >> 4;
    float wsv = ws2[c];
    float bw = g_scal[4], w0 = g_scal[5], w1 = g_scal[6];
    float lpacc = 0.f;

    for (int e = grp; e < EE; e += ngr) {
        int s = src[e], d = dst[e];
        float hs = g_h2[(size_t)s * NC + c], hd = g_h2[(size_t)d * NC + c];
        float ps = g_hlatp2[(size_t)s * NC + c], pd = g_hlatp2[(size_t)d * NC + c];
        float df = hs - hd;
        float sdf = df * df;
        float dp = ps - pd;
        float sds = dp * dp;
        float prod = ps * pd;
        float st = prod * wsv;
#pragma unroll
        for (int off = 8; off; off >>= 1) {
            sdf  += __shfl_down_sync(0xffffffffu, sdf, off, 16);
            sds  += __shfl_down_sync(0xffffffffu, sds, off, 16);
            st   += __shfl_down_sync(0xffffffffu, st, off, 16);
            prod += __shfl_down_sync(0xffffffffu, prod, off, 16);
        }
        if (c == 0) {
            float ee = g_el2[s] + g_er2[d] + st;
            float ew = expf(ee - bw * (w0 * sdf + w1 * sds)) + EPSF;
            g_ew2[e] = ew;
            atomicAdd(&g_outw2[s], ew);
            atomicAdd(&g_inw2[d], ew);
            lpacc += wts[e] * prod;
        }
    }
    redbuf[t] = lpacc;
    __syncthreads();
    for (int s2 = 128; s2; s2 >>= 1) {
        if (t < s2) redbuf[t] += redbuf[t + s2];
        __syncthreads();
    }
    if (t == 0) atomicAdd(&g_lp, redbuf[0]);
}

// ---------------- layer2 edge pass B: rst2[dst] += h2[src] * a ----------------
__global__ void k_edgeB2(const int* __restrict__ src, const int* __restrict__ dst) {
    int gt = blockIdx.x * blockDim.x + threadIdx.x;
    int sub = gt & 3;
    int grp = gt >> 2;
    int ngr = (gridDim.x * blockDim.x) >> 2;
    for (int e = grp; e < EE; e += ngr) {
        int s = src[e], d = dst[e];
        float a = rsqrtf(g_outw2[s]) * rsqrtf(g_inw2[d]) * g_ew2[e];
        float4 h = ((const float4*)(g_h2 + (size_t)s * NC))[sub];
        h.x *= a; h.y *= a; h.z *= a; h.w *= a;
        red_add_v4(&g_rst2[(size_t)d * NC + (sub << 2)], h);
    }
}

// ---------------- final: out = log_softmax(elu(rst2 + h2*perm2)); lp ----------------
__global__ void k_final(float* __restrict__ out, int out_size) {
    int t = threadIdx.x;
    int c = t & 15;
    int grp = (blockIdx.x * blockDim.x + t) >> 4;
    int ngr = (gridDim.x * blockDim.x) >> 4;
    float pc = g_scal[7];

    for (int n = grp; n < NN; n += ngr) {
        float perm = pc / (g_indeg[n] + EPSF);
        float v = g_rst2[(size_t)n * NC + c] + g_h2[(size_t)n * NC + c] * perm;
        float xv = eluf(v);
        float m = xv;
#pragma unroll
        for (int off = 8; off; off >>= 1)
            m = fmaxf(m, __shfl_xor_sync(0xffffffffu, m, off, 16));
        float ex = expf(xv - m);
        float ssum = ex;
#pragma unroll
        for (int off = 8; off; off >>= 1)
            ssum += __shfl_xor_sync(0xffffffffu, ssum, off, 16);
        out[(size_t)n * NC + c] = xv - m - logf(ssum);
    }
    if (blockIdx.x == 0 && t == 0 && out_size > NN * NC)
        out[NN * NC] = g_lp;
}

// ---------------- launch ----------------
extern "C" void kernel_launch(void* const* d_in, const int* in_sizes, int n_in,
                              void* d_out, int out_size) {
    const int*   src    = (const int*)d_in[0];
    const int*   dst    = (const int*)d_in[1];
    const float* x      = (const float*)d_in[2];
    const float* wts    = (const float*)d_in[3];
    const float* latp   = (const float*)d_in[4];
    const float* sl_w   = (const float*)d_in[5];
    const float* sl_b   = (const float*)d_in[6];
    const float* slo_w  = (const float*)d_in[7];
    const float* slo_b  = (const float*)d_in[8];
    const float* fc1_w  = (const float*)d_in[9];
    const float* w_u1   = (const float*)d_in[10];
    const float* w_v1   = (const float*)d_in[11];
    const float* w_s1   = (const float*)d_in[12];
    const float* beta1  = (const float*)d_in[13];
    const float* aw1    = (const float*)d_in[14];
    const float* theta1 = (const float*)d_in[15];
    const float* fc2_w  = (const float*)d_in[16];
    const float* w_u2   = (const float*)d_in[17];
    const float* w_v2   = (const float*)d_in[18];
    const float* w_s2   = (const float*)d_in[19];
    const float* beta2  = (const float*)d_in[20];
    const float* aw2    = (const float*)d_in[21];
    const float* theta2 = (const float*)d_in[22];
    float* out = (float*)d_out;

    k_zero<<<1024, 256>>>();
    k_scalars<<<1, 32>>>(beta1, aw1, theta1, beta2, aw2, theta2);
    k_latp<<<(NN + 255) / 256, 256>>>(latp, sl_w, sl_b, slo_w, slo_b);
    k_gemm1<<<(NN + GBM - 1) / GBM, 256>>>(x, fc1_w);
    k_eler1<<<2048, 256>>>(w_u1, w_v1);
    k_edgeA1<<<4096, 256>>>(src, dst, w_s1);
    k_edgeB1<<<4096, 256>>>(src, dst);
    k_combine1<<<2048, 256>>>();
    k_fc2<<<2048, 256>>>(fc2_w, w_u2, w_v2);
    k_edgeA2<<<2048, 256>>>(src, dst, w_s2, wts);
    k_edgeB2<<<2048, 256>>>(src, dst);
    k_final<<<2048, 256>>>(out, out_size);
}